// round 5
// baseline (speedup 1.0000x reference)
#include <cuda_runtime.h>
#include <math.h>
#include <stdint.h>

#define DDIM 2048
#define NROWS 65536
#define RPB 128                        // rows per block (attn)
#define BLKS_PER_SIDE (NROWS / RPB)    // 512
#define WARPS_PB 8
#define NSTAGES 3
#define ROWS_PER_STAGE 8               // one row per warp per stage
#define STAGE_BYTES (ROWS_PER_STAGE * DDIM * 4)   // 65536
#define NUM_STAGES_TOTAL (RPB / ROWS_PER_STAGE)   // 16
#define ALIGN_BLKS 128
#define ALIGN_ROWS (DDIM / ALIGN_BLKS) // 16
#define SGROUPS 8
#define SG_SZ (BLKS_PER_SIDE / SGROUPS)  // 64

// -------- device scratch (no allocations allowed) --------
__device__ float g_align_part[ALIGN_BLKS][2][DDIM];     // 2 MB
__device__ float g_align[2][DDIM];
__device__ float g_acc[2][BLKS_PER_SIDE][DDIM];         // 8 MB
__device__ float g_m[2][BLKS_PER_SIDE];
__device__ float g_z[2][BLKS_PER_SIDE];
__device__ float g_part[2][SGROUPS][DDIM];              // 128 KB

// -------- PTX helpers --------
__device__ __forceinline__ uint32_t smem_u32(const void* p) {
    return (uint32_t)__cvta_generic_to_shared(p);
}
#define MBAR_INIT(addr, cnt) \
    asm volatile("mbarrier.init.shared.b64 [%0], %1;" :: "r"(addr), "r"(cnt) : "memory")
#define MBAR_EXPECT_TX(addr, bytes) \
    asm volatile("mbarrier.arrive.expect_tx.shared.b64 _, [%0], %1;" :: "r"(addr), "r"(bytes) : "memory")
#define MBAR_ARRIVE(addr) \
    asm volatile("mbarrier.arrive.shared.b64 _, [%0];" :: "r"(addr) : "memory")
#define BULK_G2S(dst, src, bytes, mbar) \
    asm volatile("cp.async.bulk.shared::cta.global.mbarrier::complete_tx::bytes [%0], [%1], %2, [%3];" \
                 :: "r"(dst), "l"(src), "r"(bytes), "r"(mbar) : "memory")
#define MBAR_WAIT_PARITY(addr, parity) do {                                        \
    uint32_t _m = (addr); uint32_t _p = (parity); uint32_t _done;                  \
    asm volatile("{\n\t.reg .pred p;\n\t"                                          \
        "mbarrier.try_wait.parity.acquire.cta.shared::cta.b64 p, [%1], %2;\n\t"    \
        "selp.b32 %0, 1, 0, p;\n\t}"                                               \
        : "=r"(_done) : "r"(_m), "r"(_p) : "memory");                              \
    if (!_done) {                                                                  \
        asm volatile("{\n\t.reg .pred P1;\n\t"                                     \
            "WL_%=:\n\t"                                                           \
            "mbarrier.try_wait.parity.acquire.cta.shared::cta.b64 P1, [%0], %1, 0x989680;\n\t" \
            "@P1 bra.uni WD_%=;\n\t"                                               \
            "bra.uni WL_%=;\n\t"                                                   \
            "WD_%=:\n\t}" :: "r"(_m), "r"(_p) : "memory");                         \
    }                                                                              \
} while (0)

// ---------------------------------------------------------
// Kernel 1: partial GEMV for both sides against shared W_a.
// ---------------------------------------------------------
__global__ void align_partial(const float* __restrict__ wl,
                              const float* __restrict__ wr,
                              const float* __restrict__ Wa) {
    int b = blockIdx.x;
    int t = threadIdx.x;
    float accl[8], accr[8];
#pragma unroll
    for (int k = 0; k < 8; k++) { accl[k] = 0.f; accr[k] = 0.f; }

    int r0 = b * ALIGN_ROWS;
    for (int i = 0; i < ALIGN_ROWS; i++) {
        int row = r0 + i;
        float vl = wl[row];
        float vr = wr[row];
        const float* Wrow = Wa + (size_t)row * DDIM;
#pragma unroll
        for (int k = 0; k < 8; k++) {
            float w = Wrow[t + 256 * k];
            accl[k] = fmaf(vl, w, accl[k]);
            accr[k] = fmaf(vr, w, accr[k]);
        }
    }
#pragma unroll
    for (int k = 0; k < 8; k++) {
        g_align_part[b][0][t + 256 * k] = accl[k];
        g_align_part[b][1][t + 256 * k] = accr[k];
    }
}

// ---------------------------------------------------------
// Kernel 2: reduce align partials, add bias, tanh.
// ---------------------------------------------------------
__global__ void align_finalize(const float* __restrict__ ba) {
    int j = blockIdx.x * blockDim.x + threadIdx.x;
    float bias = ba[j];
    float sl = bias, sr = bias;
    for (int b = 0; b < ALIGN_BLKS; b++) {
        sl += g_align_part[b][0][j];
        sr += g_align_part[b][1][j];
    }
    g_align[0][j] = tanhf(sl);
    g_align[1][j] = tanhf(sr);
}

// ---------------------------------------------------------
// Kernel 3: fused score + online-softmax + weighted accumulate.
// cp.async.bulk 3-deep smem ring, full/empty mbarrier pairs.
// Warp w consumes row w of each stage; empty barriers carry
// arrive-count 8 so the producer refetch waits on consumption
// without a block-wide barrier in the loop.
// ---------------------------------------------------------
extern __shared__ float dynsmem[];     // NSTAGES * 64 KB ring; reused as merge buf

__global__ void __launch_bounds__(256, 1)
attn_fused(const float* __restrict__ candL, const float* __restrict__ candR) {
    const int side = blockIdx.y;                  // 0: left word vs candR
    const float* cand = (side == 0) ? candR : candL;
    const int blk  = blockIdx.x;
    const int tid  = threadIdx.x;
    const int warp = tid >> 5;
    const int lane = tid & 31;

    __shared__ float s_align[DDIM];               // 8 KB
    __shared__ float s_m[WARPS_PB], s_z[WARPS_PB];
    __shared__ uint64_t s_full[NSTAGES];
    __shared__ uint64_t s_empty[NSTAGES];

    for (int i = tid; i < DDIM; i += 256)
        s_align[i] = g_align[side][i];

    if (tid == 0) {
#pragma unroll
        for (int s = 0; s < NSTAGES; s++) {
            MBAR_INIT(smem_u32(&s_full[s]), 1);
            MBAR_INIT(smem_u32(&s_empty[s]), WARPS_PB);
        }
    }
    __syncthreads();

    // cache align slice in registers: lane l owns cols {4l + 128c}
    float4 al[16];
    {
        const float4* ap = reinterpret_cast<const float4*>(s_align) + lane;
#pragma unroll
        for (int c = 0; c < 16; c++) al[c] = ap[c * 32];
    }

    const float* gbase = cand + (size_t)blk * RPB * DDIM;

    // prologue: fetch stages 0..2
    if (tid == 0) {
#pragma unroll
        for (int s = 0; s < NSTAGES; s++) {
            uint32_t mb = smem_u32(&s_full[s]);
            MBAR_EXPECT_TX(mb, STAGE_BYTES);
            uint32_t dst = smem_u32(dynsmem) + s * STAGE_BYTES;
            BULK_G2S(dst, gbase + (size_t)s * ROWS_PER_STAGE * DDIM,
                     STAGE_BYTES, mb);
        }
    }

    float4 acc[16];
#pragma unroll
    for (int c = 0; c < 16; c++) acc[c] = make_float4(0.f, 0.f, 0.f, 0.f);
    float m = -1e30f, Z = 0.f;

    for (int s = 0; s < NUM_STAGES_TOTAL; s++) {
        const int slot = s % NSTAGES;
        const uint32_t par = (s / NSTAGES) & 1;
        MBAR_WAIT_PARITY(smem_u32(&s_full[slot]), par);

        const float4* rp = reinterpret_cast<const float4*>(
            dynsmem + slot * (STAGE_BYTES / 4) + warp * DDIM) + lane;

        float4 x[16];
#pragma unroll
        for (int c = 0; c < 16; c++) x[c] = rp[c * 32];

        float p0 = 0.f, p1 = 0.f, p2 = 0.f, p3 = 0.f;
#pragma unroll
        for (int c = 0; c < 16; c++) {
            p0 = fmaf(x[c].x, al[c].x, p0);
            p1 = fmaf(x[c].y, al[c].y, p1);
            p2 = fmaf(x[c].z, al[c].z, p2);
            p3 = fmaf(x[c].w, al[c].w, p3);
        }
        float p = (p0 + p1) + (p2 + p3);
#pragma unroll
        for (int o = 16; o > 0; o >>= 1)
            p += __shfl_xor_sync(0xffffffffu, p, o);

        if (p > m) {
            float c = __expf(m - p);   // first row: exp(-huge) == 0
            Z *= c;
#pragma unroll
            for (int k = 0; k < 16; k++) {
                acc[k].x *= c; acc[k].y *= c; acc[k].z *= c; acc[k].w *= c;
            }
            m = p;
        }
        float w = __expf(p - m);
        Z += w;
#pragma unroll
        for (int k = 0; k < 16; k++) {
            acc[k].x = fmaf(w, x[k].x, acc[k].x);
            acc[k].y = fmaf(w, x[k].y, acc[k].y);
            acc[k].z = fmaf(w, x[k].z, acc[k].z);
            acc[k].w = fmaf(w, x[k].w, acc[k].w);
        }

        // this warp is done with the slot
        if (lane == 0) MBAR_ARRIVE(smem_u32(&s_empty[slot]));

        // producer: refetch slot for stage s+NSTAGES once all 8 warps arrived
        if (tid == 0 && s + NSTAGES < NUM_STAGES_TOTAL) {
            MBAR_WAIT_PARITY(smem_u32(&s_empty[slot]), par);
            int sn = s + NSTAGES;
            uint32_t mb = smem_u32(&s_full[slot]);
            MBAR_EXPECT_TX(mb, STAGE_BYTES);
            uint32_t dst = smem_u32(dynsmem) + slot * STAGE_BYTES;
            BULK_G2S(dst, gbase + (size_t)sn * ROWS_PER_STAGE * DDIM,
                     STAGE_BYTES, mb);
        }
    }

    // ---- block-level merge of the 8 warp states (ring smem reused) ----
    if (lane == 0) { s_m[warp] = m; s_z[warp] = Z; }
    __syncthreads();   // also guarantees every warp finished reading the ring

    float mb2 = s_m[0];
#pragma unroll
    for (int w = 1; w < WARPS_PB; w++) mb2 = fmaxf(mb2, s_m[w]);
    float scale = __expf(m - mb2);     // warp-uniform

    float* s_acc = dynsmem;            // [WARPS_PB][DDIM], 64 KB of the ring
    float4* sa = reinterpret_cast<float4*>(s_acc + warp * DDIM) + lane;
#pragma unroll
    for (int c = 0; c < 16; c++) {
        float4 v = acc[c];
        v.x *= scale; v.y *= scale; v.z *= scale; v.w *= scale;
        sa[c * 32] = v;
    }
    __syncthreads();

    for (int j = tid; j < DDIM; j += 256) {
        float ssum = 0.f;
#pragma unroll
        for (int w = 0; w < WARPS_PB; w++) ssum += s_acc[w * DDIM + j];
        g_acc[side][blk][j] = ssum;
    }
    if (tid == 0) {
        float zb = 0.f;
#pragma unroll
        for (int w = 0; w < WARPS_PB; w++)
            zb += s_z[w] * __expf(s_m[w] - mb2);
        g_m[side][blk] = zb > 0.f ? mb2 : mb2;   // keep layout simple
        g_m[side][blk] = mb2;
        g_z[side][blk] = zb;
    }
}

// ---------------------------------------------------------
// Kernel 4: combine partials. grid (DDIM/128, SGROUPS, 2), 256 thr.
// Each block redundantly reduces the 512 (m,z) pairs from L2
// (tiny, broadcast), then reduces its 64 chunks x 128 cols and
// writes a Zi-scaled partial.
// ---------------------------------------------------------
__global__ void __launch_bounds__(256, 4)
combine_partial() {
    const int side = blockIdx.z;
    const int sg   = blockIdx.y;
    const int t    = threadIdx.x;
    const int tj   = t & 127;          // column within tile
    const int tc   = t >> 7;           // chunk half 0/1

    __shared__ float s_red[256];
    __shared__ float s_coef[SG_SZ];
    __shared__ float s_half[2][128];

    // global max over 512 chunk maxima (each thread covers 2)
    float m1 = g_m[side][t];
    float m2 = g_m[side][t + 256];
    s_red[t] = fmaxf(m1, m2);
    __syncthreads();
    for (int o = 128; o > 0; o >>= 1) {
        if (t < o) s_red[t] = fmaxf(s_red[t], s_red[t + o]);
        __syncthreads();
    }
    float M = s_red[0];
    __syncthreads();

    // normalizer
    float zv = g_z[side][t] * __expf(m1 - M) +
               g_z[side][t + 256] * __expf(m2 - M);
    s_red[t] = zv;
    __syncthreads();
    for (int o = 128; o > 0; o >>= 1) {
        if (t < o) s_red[t] += s_red[t + o];
        __syncthreads();
    }
    float Zi = 1.0f / s_red[0];

    // coefficients for this stream-group's 64 chunks
    if (t < SG_SZ)
        s_coef[t] = __expf(g_m[side][sg * SG_SZ + t] - M) * Zi;
    __syncthreads();

    const int j = blockIdx.x * 128 + tj;
    float s = 0.f;
#pragma unroll 8
    for (int c = tc * 32; c < tc * 32 + 32; c++)
        s = fmaf(s_coef[c], g_acc[side][sg * SG_SZ + c][j], s);
    s_half[tc][tj] = s;
    __syncthreads();

    if (tc == 0)
        g_part[side][sg][j] = s_half[0][tj] + s_half[1][tj];
}

// ---------------------------------------------------------
// Kernel 5: final reduce over stream groups, write out.
// out layout: [0..2047] = left result, [2048..4095] = right.
// ---------------------------------------------------------
__global__ void combine_final(float* __restrict__ out) {
    const int side = blockIdx.y;
    const int j = blockIdx.x * 256 + threadIdx.x;
    float s = 0.f;
#pragma unroll
    for (int sg = 0; sg < SGROUPS; sg++) s += g_part[side][sg][j];
    out[side * DDIM + j] = s;
}

// ---------------------------------------------------------
extern "C" void kernel_launch(void* const* d_in, const int* in_sizes, int n_in,
                              void* d_out, int out_size) {
    const float* wl    = (const float*)d_in[0];  // embed_word_l  [1, D]
    const float* wr    = (const float*)d_in[1];  // embed_word_r  [1, D]
    const float* candL = (const float*)d_in[2];  // embed_candidates_l [N, D]
    const float* candR = (const float*)d_in[3];  // embed_candidates_r [N, D]
    const float* Wa    = (const float*)d_in[4];  // W_a [D, D]
    const float* ba    = (const float*)d_in[5];  // b_a [1, D]
    float* out = (float*)d_out;

    static int smem_set = 0;   // idempotent attribute set (not a guard on work)
    if (!smem_set) {
        cudaFuncSetAttribute(attn_fused,
                             cudaFuncAttributeMaxDynamicSharedMemorySize,
                             NSTAGES * STAGE_BYTES);
        smem_set = 1;
    }

    align_partial<<<ALIGN_BLKS, 256>>>(wl, wr, Wa);
    align_finalize<<<DDIM / 256, 256>>>(ba);
    attn_fused<<<dim3(BLKS_PER_SIDE, 2), 256, NSTAGES * STAGE_BYTES>>>(candL, candR);
    combine_partial<<<dim3(DDIM / 128, SGROUPS, 2), 256>>>();
    combine_final<<<dim3(DDIM / 256, 2), 256>>>(out);
}

// round 6
// speedup vs baseline: 1.0090x; 1.0090x over previous
#include <cuda_runtime.h>
#include <math.h>
#include <stdint.h>

#define DDIM 2048
#define NROWS 65536
#define RPB 128                        // rows per block (attn)
#define BLKS_PER_SIDE (NROWS / RPB)    // 512
#define WARPS_PB 8
#define NSTAGES 3
#define ROWS_PER_STAGE 8               // one row per warp per stage
#define STAGE_BYTES (ROWS_PER_STAGE * DDIM * 4)   // 65536
#define NUM_STAGES_TOTAL (RPB / ROWS_PER_STAGE)   // 16
#define ALIGN_BLKS 256
#define ALIGN_ROWS (DDIM / ALIGN_BLKS) // 8
#define SGROUPS 16
#define SG_SZ (BLKS_PER_SIDE / SGROUPS)  // 32

// -------- device scratch (no allocations allowed) --------
__device__ float g_align_part[ALIGN_BLKS][2][DDIM];     // 4 MB
__device__ float g_align[2][DDIM];
__device__ float g_acc[2][BLKS_PER_SIDE][DDIM];         // 8 MB
__device__ float g_m[2][BLKS_PER_SIDE];
__device__ float g_z[2][BLKS_PER_SIDE];
__device__ float g_coef[2][BLKS_PER_SIDE];              // exp(m-M)/Z
__device__ float g_part[2][SGROUPS][DDIM];              // 256 KB

// -------- PTX helpers --------
__device__ __forceinline__ uint32_t smem_u32(const void* p) {
    return (uint32_t)__cvta_generic_to_shared(p);
}
#define MBAR_INIT(addr, cnt) \
    asm volatile("mbarrier.init.shared.b64 [%0], %1;" :: "r"(addr), "r"(cnt) : "memory")
#define MBAR_EXPECT_TX(addr, bytes) \
    asm volatile("mbarrier.arrive.expect_tx.shared.b64 _, [%0], %1;" :: "r"(addr), "r"(bytes) : "memory")
#define BULK_G2S(dst, src, bytes, mbar) \
    asm volatile("cp.async.bulk.shared::cta.global.mbarrier::complete_tx::bytes [%0], [%1], %2, [%3];" \
                 :: "r"(dst), "l"(src), "r"(bytes), "r"(mbar) : "memory")
#define MBAR_WAIT_PARITY(addr, parity) do {                                        \
    uint32_t _m = (addr); uint32_t _p = (parity); uint32_t _done;                  \
    asm volatile("{\n\t.reg .pred p;\n\t"                                          \
        "mbarrier.try_wait.parity.acquire.cta.shared::cta.b64 p, [%1], %2;\n\t"    \
        "selp.b32 %0, 1, 0, p;\n\t}"                                               \
        : "=r"(_done) : "r"(_m), "r"(_p) : "memory");                              \
    if (!_done) {                                                                  \
        asm volatile("{\n\t.reg .pred P1;\n\t"                                     \
            "WL_%=:\n\t"                                                           \
            "mbarrier.try_wait.parity.acquire.cta.shared::cta.b64 P1, [%0], %1, 0x989680;\n\t" \
            "@P1 bra.uni WD_%=;\n\t"                                               \
            "bra.uni WL_%=;\n\t"                                                   \
            "WD_%=:\n\t}" :: "r"(_m), "r"(_p) : "memory");                         \
    }                                                                              \
} while (0)

// ---------------------------------------------------------
// Kernel 1: partial GEMV for both sides against shared W_a.
// ---------------------------------------------------------
__global__ void align_partial(const float* __restrict__ wl,
                              const float* __restrict__ wr,
                              const float* __restrict__ Wa) {
    int b = blockIdx.x;
    int t = threadIdx.x;
    float accl[8], accr[8];
#pragma unroll
    for (int k = 0; k < 8; k++) { accl[k] = 0.f; accr[k] = 0.f; }

    int r0 = b * ALIGN_ROWS;
#pragma unroll
    for (int i = 0; i < ALIGN_ROWS; i++) {
        int row = r0 + i;
        float vl = wl[row];
        float vr = wr[row];
        const float* Wrow = Wa + (size_t)row * DDIM;
#pragma unroll
        for (int k = 0; k < 8; k++) {
            float w = Wrow[t + 256 * k];
            accl[k] = fmaf(vl, w, accl[k]);
            accr[k] = fmaf(vr, w, accr[k]);
        }
    }
#pragma unroll
    for (int k = 0; k < 8; k++) {
        g_align_part[b][0][t + 256 * k] = accl[k];
        g_align_part[b][1][t + 256 * k] = accr[k];
    }
}

// ---------------------------------------------------------
// Kernel 2: reduce align partials, add bias, tanh.
// ---------------------------------------------------------
__global__ void align_finalize(const float* __restrict__ ba) {
    int j = blockIdx.x * blockDim.x + threadIdx.x;
    float bias = ba[j];
    float sl = bias, sr = bias;
    for (int b = 0; b < ALIGN_BLKS; b++) {
        sl += g_align_part[b][0][j];
        sr += g_align_part[b][1][j];
    }
    g_align[0][j] = tanhf(sl);
    g_align[1][j] = tanhf(sr);
}

// ---------------------------------------------------------
// Kernel 3: fused score + online-softmax + weighted accumulate.
// cp.async.bulk 3-deep smem ring; __syncthreads per stage gates
// slot reuse (measured faster than mbarrier empty protocol).
// ---------------------------------------------------------
extern __shared__ float dynsmem[];     // NSTAGES * 64 KB ring; reused as merge buf

__global__ void __launch_bounds__(256, 1)
attn_fused(const float* __restrict__ candL, const float* __restrict__ candR) {
    const int side = blockIdx.y;                  // 0: left word vs candR
    const float* cand = (side == 0) ? candR : candL;
    const int blk  = blockIdx.x;
    const int tid  = threadIdx.x;
    const int warp = tid >> 5;
    const int lane = tid & 31;

    __shared__ float s_align[DDIM];               // 8 KB
    __shared__ float s_m[WARPS_PB], s_z[WARPS_PB];
    __shared__ uint64_t s_mbar[NSTAGES];

    for (int i = tid; i < DDIM; i += 256)
        s_align[i] = g_align[side][i];

    if (tid == 0) {
#pragma unroll
        for (int s = 0; s < NSTAGES; s++)
            MBAR_INIT(smem_u32(&s_mbar[s]), 1);
    }
    __syncthreads();

    // cache align slice in registers: lane l owns cols {4l + 128c}
    float4 al[16];
    {
        const float4* ap = reinterpret_cast<const float4*>(s_align) + lane;
#pragma unroll
        for (int c = 0; c < 16; c++) al[c] = ap[c * 32];
    }

    const float* gbase = cand + (size_t)blk * RPB * DDIM;

    // prologue: fetch stages 0..2
    if (tid == 0) {
#pragma unroll
        for (int s = 0; s < NSTAGES; s++) {
            uint32_t mb = smem_u32(&s_mbar[s]);
            MBAR_EXPECT_TX(mb, STAGE_BYTES);
            uint32_t dst = smem_u32(dynsmem) + s * STAGE_BYTES;
            BULK_G2S(dst, gbase + (size_t)s * ROWS_PER_STAGE * DDIM,
                     STAGE_BYTES, mb);
        }
    }

    float4 acc[16];
#pragma unroll
    for (int c = 0; c < 16; c++) acc[c] = make_float4(0.f, 0.f, 0.f, 0.f);
    float m = -1e30f, Z = 0.f;

    for (int s = 0; s < NUM_STAGES_TOTAL; s++) {
        const int slot = s % NSTAGES;
        MBAR_WAIT_PARITY(smem_u32(&s_mbar[slot]), (s / NSTAGES) & 1);

        const float4* rp = reinterpret_cast<const float4*>(
            dynsmem + slot * (STAGE_BYTES / 4) + warp * DDIM) + lane;

        float4 x[16];
#pragma unroll
        for (int c = 0; c < 16; c++) x[c] = rp[c * 32];

        float p0 = 0.f, p1 = 0.f, p2 = 0.f, p3 = 0.f;
#pragma unroll
        for (int c = 0; c < 16; c++) {
            p0 = fmaf(x[c].x, al[c].x, p0);
            p1 = fmaf(x[c].y, al[c].y, p1);
            p2 = fmaf(x[c].z, al[c].z, p2);
            p3 = fmaf(x[c].w, al[c].w, p3);
        }
        float p = (p0 + p1) + (p2 + p3);
#pragma unroll
        for (int o = 16; o > 0; o >>= 1)
            p += __shfl_xor_sync(0xffffffffu, p, o);

        if (p > m) {
            float c = __expf(m - p);   // first row: exp(-huge) == 0
            Z *= c;
#pragma unroll
            for (int k = 0; k < 16; k++) {
                acc[k].x *= c; acc[k].y *= c; acc[k].z *= c; acc[k].w *= c;
            }
            m = p;
        }
        float w = __expf(p - m);
        Z += w;
#pragma unroll
        for (int k = 0; k < 16; k++) {
            acc[k].x = fmaf(w, x[k].x, acc[k].x);
            acc[k].y = fmaf(w, x[k].y, acc[k].y);
            acc[k].z = fmaf(w, x[k].z, acc[k].z);
            acc[k].w = fmaf(w, x[k].w, acc[k].w);
        }

        __syncthreads();               // all warps done with this slot
        if (tid == 0 && s + NSTAGES < NUM_STAGES_TOTAL) {
            int sn = s + NSTAGES;
            uint32_t mb = smem_u32(&s_mbar[slot]);
            MBAR_EXPECT_TX(mb, STAGE_BYTES);
            uint32_t dst = smem_u32(dynsmem) + slot * STAGE_BYTES;
            BULK_G2S(dst, gbase + (size_t)sn * ROWS_PER_STAGE * DDIM,
                     STAGE_BYTES, mb);
        }
    }

    // ---- block-level merge of the 8 warp states (ring smem reused) ----
    if (lane == 0) { s_m[warp] = m; s_z[warp] = Z; }
    __syncthreads();

    float mb2 = s_m[0];
#pragma unroll
    for (int w = 1; w < WARPS_PB; w++) mb2 = fmaxf(mb2, s_m[w]);
    float scale = __expf(m - mb2);     // warp-uniform

    float* s_acc = dynsmem;            // [WARPS_PB][DDIM], 64 KB of the ring
    float4* sa = reinterpret_cast<float4*>(s_acc + warp * DDIM) + lane;
#pragma unroll
    for (int c = 0; c < 16; c++) {
        float4 v = acc[c];
        v.x *= scale; v.y *= scale; v.z *= scale; v.w *= scale;
        sa[c * 32] = v;
    }
    __syncthreads();

    for (int j = tid; j < DDIM; j += 256) {
        float ssum = 0.f;
#pragma unroll
        for (int w = 0; w < WARPS_PB; w++) ssum += s_acc[w * DDIM + j];
        g_acc[side][blk][j] = ssum;
    }
    if (tid == 0) {
        float zb = 0.f;
#pragma unroll
        for (int w = 0; w < WARPS_PB; w++)
            zb += s_z[w] * __expf(s_m[w] - mb2);
        g_m[side][blk] = mb2;
        g_z[side][blk] = zb;
    }
}

// ---------------------------------------------------------
// Kernel 4: softmax stats -> final coefficients, once per side.
// grid 2 x 512. Writes g_coef[side][c] = exp(m_c - M) / Z.
// ---------------------------------------------------------
__global__ void __launch_bounds__(512, 1)
softmax_stats() {
    const int side = blockIdx.x;
    const int t = threadIdx.x;
    __shared__ float sm[512];

    float mv = g_m[side][t];
    sm[t] = mv;
    __syncthreads();
    for (int o = 256; o > 0; o >>= 1) {
        if (t < o) sm[t] = fmaxf(sm[t], sm[t + o]);
        __syncthreads();
    }
    float M = sm[0];
    __syncthreads();

    float e = __expf(mv - M);
    sm[t] = g_z[side][t] * e;
    __syncthreads();
    for (int o = 256; o > 0; o >>= 1) {
        if (t < o) sm[t] += sm[t + o];
        __syncthreads();
    }
    g_coef[side][t] = e / sm[0];
}

// ---------------------------------------------------------
// Kernel 5: combine partials. grid (32 coltiles, SGROUPS, 2),
// 256 threads. Thread (f4 = t&15, part = t>>4) loads 2 chunks
// (part*2, part*2+1) of this group's 32 for one float4 column;
// 16-way smem tree reduces parts. No stats prologue — coefs
// come precomputed from g_coef (2 KB, L2 broadcast).
// ---------------------------------------------------------
__global__ void __launch_bounds__(256, 8)
combine_partial() {
    const int side = blockIdx.z;
    const int sg   = blockIdx.y;
    const int f4   = threadIdx.x & 15;   // float4 column within 64-col tile
    const int part = threadIdx.x >> 4;   // 0..15, two chunks each

    __shared__ float s_coef[SG_SZ];
    __shared__ float4 s_part[16][16];

    if (threadIdx.x < SG_SZ)
        s_coef[threadIdx.x] = g_coef[side][sg * SG_SZ + threadIdx.x];
    __syncthreads();

    const int col4 = blockIdx.x * 16 + f4;          // float4 index in [0,512)
    const int c0 = part * 2;
    const float4* a0 = reinterpret_cast<const float4*>(
        &g_acc[side][sg * SG_SZ + c0][0]) + col4;
    const float4* a1 = reinterpret_cast<const float4*>(
        &g_acc[side][sg * SG_SZ + c0 + 1][0]) + col4;

    float4 v0 = *a0;
    float4 v1 = *a1;
    float k0 = s_coef[c0], k1 = s_coef[c0 + 1];
    float4 r;
    r.x = v0.x * k0 + v1.x * k1;
    r.y = v0.y * k0 + v1.y * k1;
    r.z = v0.z * k0 + v1.z * k1;
    r.w = v0.w * k0 + v1.w * k1;
    s_part[part][f4] = r;
    __syncthreads();

#pragma unroll
    for (int o = 8; o > 0; o >>= 1) {
        if (part < o) {
            float4 a = s_part[part][f4];
            float4 b = s_part[part + o][f4];
            a.x += b.x; a.y += b.y; a.z += b.z; a.w += b.w;
            s_part[part][f4] = a;
        }
        __syncthreads();
    }

    if (part == 0)
        reinterpret_cast<float4*>(&g_part[side][sg][0])[col4] = s_part[0][f4];
}

// ---------------------------------------------------------
// Kernel 6: final reduce over chunk groups, write out.
// out layout: [0..2047] = left result, [2048..4095] = right.
// ---------------------------------------------------------
__global__ void combine_final(float* __restrict__ out) {
    const int side = blockIdx.y;
    const int j = blockIdx.x * 256 + threadIdx.x;
    float s = 0.f;
#pragma unroll
    for (int sg = 0; sg < SGROUPS; sg++) s += g_part[side][sg][j];
    out[side * DDIM + j] = s;
}

// ---------------------------------------------------------
extern "C" void kernel_launch(void* const* d_in, const int* in_sizes, int n_in,
                              void* d_out, int out_size) {
    const float* wl    = (const float*)d_in[0];  // embed_word_l  [1, D]
    const float* wr    = (const float*)d_in[1];  // embed_word_r  [1, D]
    const float* candL = (const float*)d_in[2];  // embed_candidates_l [N, D]
    const float* candR = (const float*)d_in[3];  // embed_candidates_r [N, D]
    const float* Wa    = (const float*)d_in[4];  // W_a [D, D]
    const float* ba    = (const float*)d_in[5];  // b_a [1, D]
    float* out = (float*)d_out;

    static int smem_set = 0;   // idempotent attribute set (not a guard on work)
    if (!smem_set) {
        cudaFuncSetAttribute(attn_fused,
                             cudaFuncAttributeMaxDynamicSharedMemorySize,
                             NSTAGES * STAGE_BYTES);
        smem_set = 1;
    }

    align_partial<<<ALIGN_BLKS, 256>>>(wl, wr, Wa);
    align_finalize<<<DDIM / 256, 256>>>(ba);
    attn_fused<<<dim3(BLKS_PER_SIDE, 2), 256, NSTAGES * STAGE_BYTES>>>(candL, candR);
    softmax_stats<<<2, BLKS_PER_SIDE>>>();
    combine_partial<<<dim3(DDIM / 64, SGROUPS, 2), 256>>>();
    combine_final<<<dim3(DDIM / 256, 2), 256>>>(out);
}

// round 7
// speedup vs baseline: 1.0094x; 1.0003x over previous
#include <cuda_runtime.h>
#include <math.h>
#include <stdint.h>

#define DDIM 2048
#define NROWS 65536
#define RPB 128                        // rows per segment
#define SEGS_PER_SIDE (NROWS / RPB)    // 512
#define TOTAL_SEG (2 * SEGS_PER_SIDE)  // 1024
#define GRID_ATTN 148                  // persistent: min(SM count)
#define WARPS_PB 8
#define NSTAGES 3
#define ROWS_PER_STAGE 8               // one row per warp per stage
#define STAGE_BYTES (ROWS_PER_STAGE * DDIM * 4)   // 65536
#define STAGES_PER_SEG (RPB / ROWS_PER_STAGE)     // 16
#define ALIGN_BLKS 256
#define ALIGN_ROWS (DDIM / ALIGN_BLKS) // 8

// -------- device scratch (no allocations allowed) --------
__device__ float g_align_part[ALIGN_BLKS][2][DDIM];     // 4 MB
__device__ float g_align[2][DDIM];
__device__ float g_acc[2][SEGS_PER_SIDE][DDIM];         // 8 MB
__device__ float g_m[2][SEGS_PER_SIDE];
__device__ float g_z[2][SEGS_PER_SIDE];

// -------- PTX helpers --------
__device__ __forceinline__ uint32_t smem_u32(const void* p) {
    return (uint32_t)__cvta_generic_to_shared(p);
}
#define MBAR_INIT(addr, cnt) \
    asm volatile("mbarrier.init.shared.b64 [%0], %1;" :: "r"(addr), "r"(cnt) : "memory")
#define MBAR_EXPECT_TX(addr, bytes) \
    asm volatile("mbarrier.arrive.expect_tx.shared.b64 _, [%0], %1;" :: "r"(addr), "r"(bytes) : "memory")
#define BULK_G2S(dst, src, bytes, mbar) \
    asm volatile("cp.async.bulk.shared::cta.global.mbarrier::complete_tx::bytes [%0], [%1], %2, [%3];" \
                 :: "r"(dst), "l"(src), "r"(bytes), "r"(mbar) : "memory")
#define MBAR_WAIT_PARITY(addr, parity) do {                                        \
    uint32_t _m = (addr); uint32_t _p = (parity); uint32_t _done;                  \
    asm volatile("{\n\t.reg .pred p;\n\t"                                          \
        "mbarrier.try_wait.parity.acquire.cta.shared::cta.b64 p, [%1], %2;\n\t"    \
        "selp.b32 %0, 1, 0, p;\n\t}"                                               \
        : "=r"(_done) : "r"(_m), "r"(_p) : "memory");                              \
    if (!_done) {                                                                  \
        asm volatile("{\n\t.reg .pred P1;\n\t"                                     \
            "WL_%=:\n\t"                                                           \
            "mbarrier.try_wait.parity.acquire.cta.shared::cta.b64 P1, [%0], %1, 0x989680;\n\t" \
            "@P1 bra.uni WD_%=;\n\t"                                               \
            "bra.uni WL_%=;\n\t"                                                   \
            "WD_%=:\n\t}" :: "r"(_m), "r"(_p) : "memory");                         \
    }                                                                              \
} while (0)

// ---------------------------------------------------------
// Kernel 1: partial GEMV for both sides against shared W_a.
// ---------------------------------------------------------
__global__ void align_partial(const float* __restrict__ wl,
                              const float* __restrict__ wr,
                              const float* __restrict__ Wa) {
    int b = blockIdx.x;
    int t = threadIdx.x;
    float accl[8], accr[8];
#pragma unroll
    for (int k = 0; k < 8; k++) { accl[k] = 0.f; accr[k] = 0.f; }

    int r0 = b * ALIGN_ROWS;
#pragma unroll
    for (int i = 0; i < ALIGN_ROWS; i++) {
        int row = r0 + i;
        float vl = wl[row];
        float vr = wr[row];
        const float* Wrow = Wa + (size_t)row * DDIM;
#pragma unroll
        for (int k = 0; k < 8; k++) {
            float w = Wrow[t + 256 * k];
            accl[k] = fmaf(vl, w, accl[k]);
            accr[k] = fmaf(vr, w, accr[k]);
        }
    }
#pragma unroll
    for (int k = 0; k < 8; k++) {
        g_align_part[b][0][t + 256 * k] = accl[k];
        g_align_part[b][1][t + 256 * k] = accr[k];
    }
}

// ---------------------------------------------------------
// Kernel 2: reduce align partials, add bias, tanh.
// ---------------------------------------------------------
__global__ void align_finalize(const float* __restrict__ ba) {
    int j = blockIdx.x * blockDim.x + threadIdx.x;
    float bias = ba[j];
    float sl = bias, sr = bias;
    for (int b = 0; b < ALIGN_BLKS; b++) {
        sl += g_align_part[b][0][j];
        sr += g_align_part[b][1][j];
    }
    g_align[0][j] = tanhf(sl);
    g_align[1][j] = tanhf(sr);
}

// ---------------------------------------------------------
// Kernel 3: PERSISTENT fused score + online-softmax + accumulate.
// 148 blocks; block b owns segments {b, b+148, ...} of 1024
// (segment = 128 rows; segments 0..511 = side 0 (candR),
// 512..1023 = side 1 (candL)). The 3-deep cp.async.bulk ring runs
// continuously across segment boundaries; at each segment end the
// just-consumed slot is reused as the 64 KB warp-merge buffer and
// its refetch is issued after the merge completes.
// ---------------------------------------------------------
extern __shared__ float dynsmem[];     // NSTAGES * 64 KB ring

__device__ __forceinline__ void fetch_stage(int b, int g,
                                            const float* __restrict__ candL,
                                            const float* __restrict__ candR,
                                            uint64_t* s_mbar, float* dyn) {
    int k = g >> 4;                    // segment ordinal within block
    int S = b + k * GRID_ATTN;         // global segment id
    int side = S >> 9;
    int seg  = S & 511;
    const float* cand = side ? candL : candR;
    const float* src = cand + ((size_t)seg * RPB + (g & 15) * ROWS_PER_STAGE) * DDIM;
    int slot = g % NSTAGES;
    uint32_t mb = smem_u32(&s_mbar[slot]);
    MBAR_EXPECT_TX(mb, STAGE_BYTES);
    BULK_G2S(smem_u32(dyn) + slot * STAGE_BYTES, src, STAGE_BYTES, mb);
}

__global__ void __launch_bounds__(256, 1)
attn_persistent(const float* __restrict__ candL, const float* __restrict__ candR) {
    const int b    = blockIdx.x;
    const int tid  = threadIdx.x;
    const int warp = tid >> 5;
    const int lane = tid & 31;

    __shared__ float s_align[2][DDIM];            // 16 KB, both sides
    __shared__ float s_m[WARPS_PB], s_z[WARPS_PB];
    __shared__ uint64_t s_mbar[NSTAGES];

    for (int i = tid; i < 2 * DDIM; i += 256)
        (&s_align[0][0])[i] = (&g_align[0][0])[i];

    if (tid == 0) {
#pragma unroll
        for (int s = 0; s < NSTAGES; s++)
            MBAR_INIT(smem_u32(&s_mbar[s]), 1);
    }
    __syncthreads();

    const int nseg = (TOTAL_SEG - b + GRID_ATTN - 1) / GRID_ATTN;  // 6 or 7
    const int total_stages = nseg * STAGES_PER_SEG;

    // align slice registers for current side (all first segments are side 0)
    int side_cur = 0;
    float4 al[16];
    {
        const float4* ap = reinterpret_cast<const float4*>(&s_align[0][0]) + lane;
#pragma unroll
        for (int c = 0; c < 16; c++) al[c] = ap[c * 32];
    }

    if (tid == 0) {
#pragma unroll
        for (int g = 0; g < NSTAGES; g++)
            fetch_stage(b, g, candL, candR, s_mbar, dynsmem);
    }

    float4 acc[16];
#pragma unroll
    for (int c = 0; c < 16; c++) acc[c] = make_float4(0.f, 0.f, 0.f, 0.f);
    float m = -1e30f, Z = 0.f;

    for (int g = 0; g < total_stages; g++) {
        const int slot = g % NSTAGES;
        MBAR_WAIT_PARITY(smem_u32(&s_mbar[slot]), (g / NSTAGES) & 1);

        const float4* rp = reinterpret_cast<const float4*>(
            dynsmem + slot * (STAGE_BYTES / 4) + warp * DDIM) + lane;

        float4 x[16];
#pragma unroll
        for (int c = 0; c < 16; c++) x[c] = rp[c * 32];

        float p0 = 0.f, p1 = 0.f, p2 = 0.f, p3 = 0.f;
#pragma unroll
        for (int c = 0; c < 16; c++) {
            p0 = fmaf(x[c].x, al[c].x, p0);
            p1 = fmaf(x[c].y, al[c].y, p1);
            p2 = fmaf(x[c].z, al[c].z, p2);
            p3 = fmaf(x[c].w, al[c].w, p3);
        }
        float p = (p0 + p1) + (p2 + p3);
#pragma unroll
        for (int o = 16; o > 0; o >>= 1)
            p += __shfl_xor_sync(0xffffffffu, p, o);

        if (p > m) {
            float c = __expf(m - p);   // first row of segment: exp(-huge) == 0
            Z *= c;
#pragma unroll
            for (int k = 0; k < 16; k++) {
                acc[k].x *= c; acc[k].y *= c; acc[k].z *= c; acc[k].w *= c;
            }
            m = p;
        }
        float w = __expf(p - m);
        Z += w;
#pragma unroll
        for (int k = 0; k < 16; k++) {
            acc[k].x = fmaf(w, x[k].x, acc[k].x);
            acc[k].y = fmaf(w, x[k].y, acc[k].y);
            acc[k].z = fmaf(w, x[k].z, acc[k].z);
            acc[k].w = fmaf(w, x[k].w, acc[k].w);
        }

        if ((g & 15) != 15) {
            // mid-segment: release slot and refetch
            __syncthreads();
            if (tid == 0 && g + NSTAGES < total_stages)
                fetch_stage(b, g + NSTAGES, candL, candR, s_mbar, dynsmem);
        } else {
            // ---- segment end: merge 8 warp states in the freed slot ----
            if (lane == 0) { s_m[warp] = m; s_z[warp] = Z; }
            __syncthreads();          // slot consumed by all warps + s_m visible

            float mb2 = s_m[0];
#pragma unroll
            for (int w2 = 1; w2 < WARPS_PB; w2++) mb2 = fmaxf(mb2, s_m[w2]);
            float scale = __expf(m - mb2);    // warp-uniform

            float* s_acc = dynsmem + slot * (STAGE_BYTES / 4);  // 64 KB
            float4* sa = reinterpret_cast<float4*>(s_acc + warp * DDIM) + lane;
#pragma unroll
            for (int c = 0; c < 16; c++) {
                float4 v = acc[c];
                v.x *= scale; v.y *= scale; v.z *= scale; v.w *= scale;
                sa[c * 32] = v;
            }
            __syncthreads();

            const int S = b + (g >> 4) * GRID_ATTN;
            const int side = S >> 9;
            const int seg  = S & 511;
            for (int j = tid; j < DDIM; j += 256) {
                float ssum = 0.f;
#pragma unroll
                for (int w2 = 0; w2 < WARPS_PB; w2++) ssum += s_acc[w2 * DDIM + j];
                g_acc[side][seg][j] = ssum;
            }
            if (tid == 0) {
                float zb = 0.f;
#pragma unroll
                for (int w2 = 0; w2 < WARPS_PB; w2++)
                    zb += s_z[w2] * __expf(s_m[w2] - mb2);
                g_m[side][seg] = mb2;
                g_z[side][seg] = zb;
            }

            // reset state for next segment
#pragma unroll
            for (int c = 0; c < 16; c++) acc[c] = make_float4(0.f, 0.f, 0.f, 0.f);
            m = -1e30f; Z = 0.f;

            // side switch for next segment (monotonic, at most once)
            if (g + 1 < total_stages) {
                int nside = (b + ((g + 1) >> 4) * GRID_ATTN) >> 9;
                if (nside != side_cur) {
                    side_cur = nside;
                    const float4* ap =
                        reinterpret_cast<const float4*>(&s_align[side_cur][0]) + lane;
#pragma unroll
                    for (int c = 0; c < 16; c++) al[c] = ap[c * 32];
                }
            }

            __syncthreads();          // merge buffer fully read -> slot reusable
            if (tid == 0 && g + NSTAGES < total_stages)
                fetch_stage(b, g + NSTAGES, candL, candR, s_mbar, dynsmem);
        }
    }
}

// ---------------------------------------------------------
// Kernel 4: single tail kernel. grid (32, 2), 256 threads.
// Shuffle-based redundant softmax stats (3 barriers), coefs in
// smem, then 16-way chunk-partitioned reduction of g_acc for a
// 64-column tile; writes out directly.
// out layout: [0..2047] = left result, [2048..4095] = right.
// ---------------------------------------------------------
__global__ void __launch_bounds__(256, 4)
combine_all(float* __restrict__ out) {
    const int side = blockIdx.y;
    const int t    = threadIdx.x;
    const int warp = t >> 5, lane = t & 31;
    const int f4   = t & 15;           // float4 column within 64-col tile
    const int part = t >> 4;           // 0..15, 32 chunks each

    __shared__ float s_red[8];
    __shared__ float s_coef[SEGS_PER_SIDE];
    __shared__ float4 s_part[16][16];

    // --- stats: global max ---
    float m1 = g_m[side][t];
    float m2 = g_m[side][t + 256];
    float mv = fmaxf(m1, m2);
#pragma unroll
    for (int o = 16; o > 0; o >>= 1)
        mv = fmaxf(mv, __shfl_xor_sync(0xffffffffu, mv, o));
    if (lane == 0) s_red[warp] = mv;
    __syncthreads();
    float M = s_red[0];
#pragma unroll
    for (int w = 1; w < 8; w++) M = fmaxf(M, s_red[w]);
    __syncthreads();

    // --- stats: normalizer ---
    float e1 = __expf(m1 - M), e2 = __expf(m2 - M);
    float zv = g_z[side][t] * e1 + g_z[side][t + 256] * e2;
#pragma unroll
    for (int o = 16; o > 0; o >>= 1)
        zv += __shfl_xor_sync(0xffffffffu, zv, o);
    if (lane == 0) s_red[warp] = zv;
    __syncthreads();
    float Zt = 0.f;
#pragma unroll
    for (int w = 1; w < 8; w++) Zt += s_red[w];
    Zt += s_red[0];
    float Zi = 1.0f / Zt;

    s_coef[t]       = e1 * Zi;
    s_coef[t + 256] = e2 * Zi;
    __syncthreads();

    // --- combine: 16 parts x 32 chunks each ---
    const int col4 = blockIdx.x * 16 + f4;          // float4 col in [0,512)
    const float4* ap = reinterpret_cast<const float4*>(&g_acc[side][0][0]) + col4;

    float4 s = make_float4(0.f, 0.f, 0.f, 0.f);
#pragma unroll 8
    for (int c = part * 32; c < part * 32 + 32; c++) {
        float4 v = ap[(size_t)c * (DDIM / 4)];
        float k = s_coef[c];
        s.x = fmaf(k, v.x, s.x);
        s.y = fmaf(k, v.y, s.y);
        s.z = fmaf(k, v.z, s.z);
        s.w = fmaf(k, v.w, s.w);
    }
    s_part[part][f4] = s;
    __syncthreads();

#pragma unroll
    for (int o = 8; o > 0; o >>= 1) {
        if (part < o) {
            float4 a = s_part[part][f4];
            float4 bb = s_part[part + o][f4];
            a.x += bb.x; a.y += bb.y; a.z += bb.z; a.w += bb.w;
            s_part[part][f4] = a;
        }
        __syncthreads();
    }

    if (part == 0)
        reinterpret_cast<float4*>(out)[side * (DDIM / 4) + col4] = s_part[0][f4];
}

// ---------------------------------------------------------
extern "C" void kernel_launch(void* const* d_in, const int* in_sizes, int n_in,
                              void* d_out, int out_size) {
    const float* wl    = (const float*)d_in[0];  // embed_word_l  [1, D]
    const float* wr    = (const float*)d_in[1];  // embed_word_r  [1, D]
    const float* candL = (const float*)d_in[2];  // embed_candidates_l [N, D]
    const float* candR = (const float*)d_in[3];  // embed_candidates_r [N, D]
    const float* Wa    = (const float*)d_in[4];  // W_a [D, D]
    const float* ba    = (const float*)d_in[5];  // b_a [1, D]
    float* out = (float*)d_out;

    static int smem_set = 0;   // idempotent attribute set (not a guard on work)
    if (!smem_set) {
        cudaFuncSetAttribute(attn_persistent,
                             cudaFuncAttributeMaxDynamicSharedMemorySize,
                             NSTAGES * STAGE_BYTES);
        smem_set = 1;
    }

    align_partial<<<ALIGN_BLKS, 256>>>(wl, wr, Wa);
    align_finalize<<<DDIM / 256, 256>>>(ba);
    attn_persistent<<<GRID_ATTN, 256, NSTAGES * STAGE_BYTES>>>(candL, candR);
    combine_all<<<dim3(DDIM / 64, 2), 256>>>(out);
}

// round 8
// speedup vs baseline: 1.0660x; 1.0561x over previous
#include <cuda_runtime.h>
#include <math.h>
#include <stdint.h>

#define DDIM 2048
#define NROWS 65536
#define WARPS_PB 8
#define NSTAGES 3
#define ROWS_PER_STAGE 8               // one row per warp per stage
#define STAGE_BYTES (ROWS_PER_STAGE * DDIM * 4)   // 65536
#define STAGE_UNITS (NROWS / ROWS_PER_STAGE)      // 8192 per side
#define MAX_CHUNKS 96                  // >= blocks per side for any SM count
#define ALIGN_BLKS 256
#define ALIGN_ROWS (DDIM / ALIGN_BLKS) // 8

// -------- device scratch (no allocations allowed) --------
__device__ float g_align_part[ALIGN_BLKS][2][DDIM];     // 4 MB
__device__ float g_align[2][DDIM];
__device__ float g_acc[2][MAX_CHUNKS][DDIM];            // 1.5 MB
__device__ float g_m[2][MAX_CHUNKS];
__device__ float g_z[2][MAX_CHUNKS];

// -------- PTX helpers --------
__device__ __forceinline__ uint32_t smem_u32(const void* p) {
    return (uint32_t)__cvta_generic_to_shared(p);
}
#define MBAR_INIT(addr, cnt) \
    asm volatile("mbarrier.init.shared.b64 [%0], %1;" :: "r"(addr), "r"(cnt) : "memory")
#define MBAR_EXPECT_TX(addr, bytes) \
    asm volatile("mbarrier.arrive.expect_tx.shared.b64 _, [%0], %1;" :: "r"(addr), "r"(bytes) : "memory")
#define BULK_G2S(dst, src, bytes, mbar) \
    asm volatile("cp.async.bulk.shared::cta.global.mbarrier::complete_tx::bytes [%0], [%1], %2, [%3];" \
                 :: "r"(dst), "l"(src), "r"(bytes), "r"(mbar) : "memory")
#define MBAR_WAIT_PARITY(addr, parity) do {                                        \
    uint32_t _m = (addr); uint32_t _p = (parity); uint32_t _done;                  \
    asm volatile("{\n\t.reg .pred p;\n\t"                                          \
        "mbarrier.try_wait.parity.acquire.cta.shared::cta.b64 p, [%1], %2;\n\t"    \
        "selp.b32 %0, 1, 0, p;\n\t}"                                               \
        : "=r"(_done) : "r"(_m), "r"(_p) : "memory");                              \
    if (!_done) {                                                                  \
        asm volatile("{\n\t.reg .pred P1;\n\t"                                     \
            "WL_%=:\n\t"                                                           \
            "mbarrier.try_wait.parity.acquire.cta.shared::cta.b64 P1, [%0], %1, 0x989680;\n\t" \
            "@P1 bra.uni WD_%=;\n\t"                                               \
            "bra.uni WL_%=;\n\t"                                                   \
            "WD_%=:\n\t}" :: "r"(_m), "r"(_p) : "memory");                         \
    }                                                                              \
} while (0)

// ---------------------------------------------------------
// Kernel 1: partial GEMV for both sides against shared W_a.
// ---------------------------------------------------------
__global__ void align_partial(const float* __restrict__ wl,
                              const float* __restrict__ wr,
                              const float* __restrict__ Wa) {
    int b = blockIdx.x;
    int t = threadIdx.x;
    float accl[8], accr[8];
#pragma unroll
    for (int k = 0; k < 8; k++) { accl[k] = 0.f; accr[k] = 0.f; }

    int r0 = b * ALIGN_ROWS;
#pragma unroll
    for (int i = 0; i < ALIGN_ROWS; i++) {
        int row = r0 + i;
        float vl = wl[row];
        float vr = wr[row];
        const float* Wrow = Wa + (size_t)row * DDIM;
#pragma unroll
        for (int k = 0; k < 8; k++) {
            float w = Wrow[t + 256 * k];
            accl[k] = fmaf(vl, w, accl[k]);
            accr[k] = fmaf(vr, w, accr[k]);
        }
    }
#pragma unroll
    for (int k = 0; k < 8; k++) {
        g_align_part[b][0][t + 256 * k] = accl[k];
        g_align_part[b][1][t + 256 * k] = accr[k];
    }
}

// ---------------------------------------------------------
// Kernel 2: reduce align partials, add bias, tanh.
// ---------------------------------------------------------
__global__ void align_finalize(const float* __restrict__ ba) {
    int j = blockIdx.x * blockDim.x + threadIdx.x;
    float bias = ba[j];
    float sl = bias, sr = bias;
    for (int b = 0; b < ALIGN_BLKS; b++) {
        sl += g_align_part[b][0][j];
        sr += g_align_part[b][1][j];
    }
    g_align[0][j] = tanhf(sl);
    g_align[1][j] = tanhf(sr);
}

// ---------------------------------------------------------
// Kernel 3: LONG-STREAM fused score + online-softmax + accumulate.
// gridDim.x blocks (== SM count, even). Blocks [0, H) handle side 0
// (word_l vs candR), blocks [H, 2H) side 1, H = gridDim.x/2.
// Block i within its side owns contiguous stage-units
// [i*8192/H, (i+1)*8192/H) (stage = 8 rows; ~110 stages each).
// The 3-deep cp.async.bulk ring runs uninterrupted over all of
// them; exactly ONE 8-warp merge per block at the end.
// ---------------------------------------------------------
extern __shared__ float dynsmem[];     // NSTAGES * 64 KB ring; slot 0 reused for merge

__global__ void __launch_bounds__(256, 1)
attn_stream(const float* __restrict__ candL, const float* __restrict__ candR) {
    const int H    = gridDim.x >> 1;
    const int side = (blockIdx.x >= H) ? 1 : 0;
    const int idx  = blockIdx.x - side * H;
    const float* cand = side ? candL : candR;
    const int tid  = threadIdx.x;
    const int warp = tid >> 5;
    const int lane = tid & 31;

    const int s0 = (int)(((long long)idx * STAGE_UNITS) / H);
    const int s1 = (int)(((long long)(idx + 1) * STAGE_UNITS) / H);
    const int ns = s1 - s0;            // ~110 stages

    __shared__ float s_align[DDIM];    // 8 KB (this block's side only)
    __shared__ float s_m[WARPS_PB], s_z[WARPS_PB];
    __shared__ uint64_t s_mbar[NSTAGES];

    for (int i = tid; i < DDIM; i += 256)
        s_align[i] = g_align[side][i];

    if (tid == 0) {
#pragma unroll
        for (int s = 0; s < NSTAGES; s++)
            MBAR_INIT(smem_u32(&s_mbar[s]), 1);
    }
    __syncthreads();

    // align slice in registers: lane l owns cols {4l + 128c}
    float4 al[16];
    {
        const float4* ap = reinterpret_cast<const float4*>(s_align) + lane;
#pragma unroll
        for (int c = 0; c < 16; c++) al[c] = ap[c * 32];
    }

    // prologue: fetch up to 3 stages
    if (tid == 0) {
        int pre = ns < NSTAGES ? ns : NSTAGES;
        for (int g = 0; g < pre; g++) {
            uint32_t mb = smem_u32(&s_mbar[g]);
            MBAR_EXPECT_TX(mb, STAGE_BYTES);
            BULK_G2S(smem_u32(dynsmem) + g * STAGE_BYTES,
                     cand + (size_t)(s0 + g) * ROWS_PER_STAGE * DDIM,
                     STAGE_BYTES, mb);
        }
    }

    float4 acc[16];
#pragma unroll
    for (int c = 0; c < 16; c++) acc[c] = make_float4(0.f, 0.f, 0.f, 0.f);
    float m = -1e30f, Z = 0.f;

    for (int g = 0; g < ns; g++) {
        const int slot = g % NSTAGES;
        MBAR_WAIT_PARITY(smem_u32(&s_mbar[slot]), (g / NSTAGES) & 1);

        const float4* rp = reinterpret_cast<const float4*>(
            dynsmem + slot * (STAGE_BYTES / 4) + warp * DDIM) + lane;

        float4 x[16];
#pragma unroll
        for (int c = 0; c < 16; c++) x[c] = rp[c * 32];

        float p0 = 0.f, p1 = 0.f, p2 = 0.f, p3 = 0.f;
#pragma unroll
        for (int c = 0; c < 16; c++) {
            p0 = fmaf(x[c].x, al[c].x, p0);
            p1 = fmaf(x[c].y, al[c].y, p1);
            p2 = fmaf(x[c].z, al[c].z, p2);
            p3 = fmaf(x[c].w, al[c].w, p3);
        }
        float p = (p0 + p1) + (p2 + p3);
#pragma unroll
        for (int o = 16; o > 0; o >>= 1)
            p += __shfl_xor_sync(0xffffffffu, p, o);

        if (p > m) {
            float c = __expf(m - p);   // first row: exp(-huge) == 0
            Z *= c;
#pragma unroll
            for (int k = 0; k < 16; k++) {
                acc[k].x *= c; acc[k].y *= c; acc[k].z *= c; acc[k].w *= c;
            }
            m = p;
        }
        float w = __expf(p - m);
        Z += w;
#pragma unroll
        for (int k = 0; k < 16; k++) {
            acc[k].x = fmaf(w, x[k].x, acc[k].x);
            acc[k].y = fmaf(w, x[k].y, acc[k].y);
            acc[k].z = fmaf(w, x[k].z, acc[k].z);
            acc[k].w = fmaf(w, x[k].w, acc[k].w);
        }

        __syncthreads();               // all warps done with this slot
        if (tid == 0 && g + NSTAGES < ns) {
            uint32_t mb = smem_u32(&s_mbar[slot]);
            MBAR_EXPECT_TX(mb, STAGE_BYTES);
            BULK_G2S(smem_u32(dynsmem) + slot * STAGE_BYTES,
                     cand + (size_t)(s0 + g + NSTAGES) * ROWS_PER_STAGE * DDIM,
                     STAGE_BYTES, mb);
        }
    }

    // ---- ONE block-level merge of the 8 warp states ----
    if (lane == 0) { s_m[warp] = m; s_z[warp] = Z; }
    __syncthreads();

    float mb2 = s_m[0];
#pragma unroll
    for (int w = 1; w < WARPS_PB; w++) mb2 = fmaxf(mb2, s_m[w]);
    float scale = __expf(m - mb2);     // warp-uniform

    float* s_acc = dynsmem;            // 64 KB merge buffer (ring slot 0)
    float4* sa = reinterpret_cast<float4*>(s_acc + warp * DDIM) + lane;
#pragma unroll
    for (int c = 0; c < 16; c++) {
        float4 v = acc[c];
        v.x *= scale; v.y *= scale; v.z *= scale; v.w *= scale;
        sa[c * 32] = v;
    }
    __syncthreads();

    for (int j = tid; j < DDIM; j += 256) {
        float ssum = 0.f;
#pragma unroll
        for (int w = 0; w < WARPS_PB; w++) ssum += s_acc[w * DDIM + j];
        g_acc[side][idx][j] = ssum;
    }
    if (tid == 0) {
        float zb = 0.f;
#pragma unroll
        for (int w = 0; w < WARPS_PB; w++)
            zb += s_z[w] * __expf(s_m[w] - mb2);
        g_m[side][idx] = mb2;
        g_z[side][idx] = zb;
    }
}

// ---------------------------------------------------------
// Kernel 4: single tail kernel. grid (32, 2), 256 threads.
// H chunks per side (~74-76). Stats over H entries are tiny:
// every thread serially reduces the smem copies (~H LDS), then
// 16-way chunk-partitioned reduction of g_acc for a 64-col tile.
// out layout: [0..2047] = left result, [2048..4095] = right.
// ---------------------------------------------------------
__global__ void __launch_bounds__(256, 4)
combine_all(float* __restrict__ out, int H) {
    const int side = blockIdx.y;
    const int t    = threadIdx.x;
    const int f4   = t & 15;           // float4 column within 64-col tile
    const int part = t >> 4;           // 0..15

    __shared__ float s_mv[MAX_CHUNKS];
    __shared__ float s_zv[MAX_CHUNKS];
    __shared__ float s_coef[MAX_CHUNKS];
    __shared__ float4 s_part[16][16];

    if (t < H) { s_mv[t] = g_m[side][t]; s_zv[t] = g_z[side][t]; }
    __syncthreads();

    float M = -1e30f;
    for (int c = 0; c < H; c++) M = fmaxf(M, s_mv[c]);
    float Zt = 0.f;
    for (int c = 0; c < H; c++) Zt += s_zv[c] * __expf(s_mv[c] - M);
    float Zi = 1.0f / Zt;
    if (t < H) s_coef[t] = __expf(s_mv[t] - M) * Zi;
    __syncthreads();

    const int col4 = blockIdx.x * 16 + f4;          // float4 col in [0,512)
    const float4* ap = reinterpret_cast<const float4*>(&g_acc[side][0][0]) + col4;

    float4 s = make_float4(0.f, 0.f, 0.f, 0.f);
    for (int c = part; c < H; c += 16) {
        float4 v = ap[(size_t)c * (DDIM / 4)];
        float k = s_coef[c];
        s.x = fmaf(k, v.x, s.x);
        s.y = fmaf(k, v.y, s.y);
        s.z = fmaf(k, v.z, s.z);
        s.w = fmaf(k, v.w, s.w);
    }
    s_part[part][f4] = s;
    __syncthreads();

#pragma unroll
    for (int o = 8; o > 0; o >>= 1) {
        if (part < o) {
            float4 a = s_part[part][f4];
            float4 bb = s_part[part + o][f4];
            a.x += bb.x; a.y += bb.y; a.z += bb.z; a.w += bb.w;
            s_part[part][f4] = a;
        }
        __syncthreads();
    }

    if (part == 0)
        reinterpret_cast<float4*>(out)[side * (DDIM / 4) + col4] = s_part[0][f4];
}

// ---------------------------------------------------------
extern "C" void kernel_launch(void* const* d_in, const int* in_sizes, int n_in,
                              void* d_out, int out_size) {
    const float* wl    = (const float*)d_in[0];  // embed_word_l  [1, D]
    const float* wr    = (const float*)d_in[1];  // embed_word_r  [1, D]
    const float* candL = (const float*)d_in[2];  // embed_candidates_l [N, D]
    const float* candR = (const float*)d_in[3];  // embed_candidates_r [N, D]
    const float* Wa    = (const float*)d_in[4];  // W_a [D, D]
    const float* ba    = (const float*)d_in[5];  // b_a [1, D]
    float* out = (float*)d_out;

    static int grid_attn = 0;          // set once; deterministic per device
    if (!grid_attn) {
        int sm = 0;
        cudaDeviceGetAttribute(&sm, cudaDevAttrMultiProcessorCount, 0);
        if (sm <= 0) sm = 148;
        grid_attn = sm & ~1;           // even: half per side
        if (grid_attn > 2 * MAX_CHUNKS) grid_attn = 2 * MAX_CHUNKS;
        cudaFuncSetAttribute(attn_stream,
                             cudaFuncAttributeMaxDynamicSharedMemorySize,
                             NSTAGES * STAGE_BYTES);
    }
    const int H = grid_attn / 2;

    align_partial<<<ALIGN_BLKS, 256>>>(wl, wr, Wa);
    align_finalize<<<DDIM / 256, 256>>>(ba);
    attn_stream<<<grid_attn, 256, NSTAGES * STAGE_BYTES>>>(candL, candR);
    combine_all<<<dim3(DDIM / 64, 2), 256>>>(out, H);
}